// round 6
// baseline (speedup 1.0000x reference)
#include <cuda_runtime.h>

// Problem constants (fixed: P=64, K=8, C=512, N=1536)
#define NROWS 1536
#define CDIM  512
#define MCL   192
#define GK    8
#define MARGIN_KL 6.0f
#define MID_N 1024
#define MID_M 128
#define GBI   48
#define GBJ   3
#define NZ    4                     // (matrix 0/1) x (K-half 0/1)
#define NBLK  (GBI * GBJ * NZ)      // 576 blocks; 4 CTAs/SM x 148 = 592 slots
#define KHALF 256

// Static device scratch
__device__ float g_xs[NROWS * CDIM];
__device__ float g_rowc[NROWS];            // ent_x + lse
__device__ float g_hcT[CDIM * MCL];        // hcen^T k-major
__device__ float g_lhT[CDIM * MCL];        // logh^T k-major
__device__ float g_enth[MCL];
__device__ float g_pd[NZ * NROWS * MCL];   // 4 partial planes
__device__ float g_part[NBLK * 4];
__device__ unsigned int g_ctr  = 0;
__device__ unsigned int g_bcnt = 0;
__device__ unsigned int g_bgen = 0;        // monotonically increasing generation

// ---------------- packed f32x2 helpers ----------------
__device__ __forceinline__ void fma2(unsigned long long& d,
                                     unsigned long long a, unsigned long long b) {
    asm("fma.rn.f32x2 %0, %1, %2, %0;" : "+l"(d) : "l"(a), "l"(b));
}
__device__ __forceinline__ void upk2(unsigned long long v, float& lo, float& hi) {
    asm("mov.b64 {%0, %1}, %2;" : "=f"(lo), "=f"(hi) : "l"(v));
}

// ---------------- grid barrier over NBLK co-resident blocks ----------------
__device__ __forceinline__ void grid_sync_all() {
    __syncthreads();
    if (threadIdx.x == 0) {
        const unsigned int gen = ((volatile unsigned int*)&g_bgen)[0];
        __threadfence();
        if (atomicAdd(&g_bcnt, 1u) == NBLK - 1) {
            g_bcnt = 0;
            __threadfence();
            atomicExch(&g_bgen, gen + 1u);
        } else {
            while (((volatile unsigned int*)&g_bgen)[0] == gen) __nanosleep(32);
        }
        __threadfence();
    }
    __syncthreads();
}

// ---------------------------------------------------------------------------
// Kernel 1: fused softmax stats + centers (fast-math exp/log). 192 x 256.
// ---------------------------------------------------------------------------
__global__ void __launch_bounds__(256) k_stats(const float* __restrict__ x) {
    __shared__ float sxs[8][516];
    __shared__ float sred[8];
    const int j = blockIdx.x;
    const int t = threadIdx.x;
    const int w = t >> 5, lane = t & 31;
    const int row = j * GK + w;

    const float4* xr = reinterpret_cast<const float4*>(x + (size_t)row * CDIM);
    float4 v[4];
    #pragma unroll
    for (int q = 0; q < 4; q++) v[q] = xr[lane + 32 * q];

    float mx = -1e30f;
    #pragma unroll
    for (int q = 0; q < 4; q++)
        mx = fmaxf(mx, fmaxf(fmaxf(v[q].x, v[q].y), fmaxf(v[q].z, v[q].w)));
    #pragma unroll
    for (int o = 16; o; o >>= 1) mx = fmaxf(mx, __shfl_xor_sync(0xffffffffu, mx, o));

    float4 e[4];
    float s = 0.f;
    #pragma unroll
    for (int q = 0; q < 4; q++) {
        e[q].x = __expf(v[q].x - mx); e[q].y = __expf(v[q].y - mx);
        e[q].z = __expf(v[q].z - mx); e[q].w = __expf(v[q].w - mx);
        s += (e[q].x + e[q].y) + (e[q].z + e[q].w);
    }
    #pragma unroll
    for (int o = 16; o; o >>= 1) s += __shfl_xor_sync(0xffffffffu, s, o);

    const float lse = mx + __logf(s);
    const float inv = 1.0f / s;

    float4* gx = reinterpret_cast<float4*>(g_xs + (size_t)row * CDIM);
    float4* sx = reinterpret_cast<float4*>(&sxs[w][0]);
    float ent = 0.f;
    #pragma unroll
    for (int q = 0; q < 4; q++) {
        float4 p = make_float4(e[q].x * inv, e[q].y * inv, e[q].z * inv, e[q].w * inv);
        gx[lane + 32 * q] = p;
        sx[lane + 32 * q] = p;
        ent += p.x * (v[q].x - lse) + p.y * (v[q].y - lse)
             + p.z * (v[q].z - lse) + p.w * (v[q].w - lse);
    }
    #pragma unroll
    for (int o = 16; o; o >>= 1) ent += __shfl_xor_sync(0xffffffffu, ent, o);
    if (lane == 0) g_rowc[row] = ent + lse;

    __syncthreads();

    float entp = 0.f;
    #pragma unroll
    for (int h = 0; h < 2; h++) {
        const int c = t + 256 * h;
        float hc = 0.f;
        #pragma unroll
        for (int r = 0; r < GK; r++) hc += sxs[r][c];
        hc *= (1.0f / (float)GK);
        const float l = __logf(fmaxf(hc, 1e-9f));
        g_hcT[c * MCL + j] = hc;
        g_lhT[c * MCL + j] = l;
        entp += hc * l;
    }
    #pragma unroll
    for (int o = 16; o; o >>= 1) entp += __shfl_xor_sync(0xffffffffu, entp, o);
    if (lane == 0) sred[w] = entp;
    __syncthreads();
    if (t == 0) {
        float eh = 0.f;
        #pragma unroll
        for (int r = 0; r < 8; r++) eh += sred[r];
        g_enth[j] = eh;
    }
}

// ---------------------------------------------------------------------------
// Kernel 2: z-split GEMM (matrix x K-half), pre-duplicated A smem layout,
// zero-MOV f32x2 inner loop + grid barrier + epilogue + final reduce.
// Grid (48, 3, 4) = 576 blocks, 128 threads, 4 CTAs/SM.
// ---------------------------------------------------------------------------
__global__ void __launch_bounds__(128, 4) k_gemm_epi(const float* __restrict__ x,
                                                     const long long* __restrict__ pids,
                                                     float* __restrict__ out) {
    __shared__ float sad[32][68];  // [kk][2*row dup], pad 68
    __shared__ float sb[32][64];   // [kk][j]
    __shared__ float rp[4], rn[4];
    __shared__ int cp[4], cn[4];
    __shared__ bool slast;

    const int bi = blockIdx.x;     // 0..47 (32-row tile)
    const int bj = blockIdx.y;     // 0..2  (64-col tile)
    const int z  = blockIdx.z;     // 0..3
    const int m  = z & 1;          // matrix select
    const int kh = z >> 1;         // K-half
    const int t  = threadIdx.x;
    const int ti = t >> 4;         // 0..7 : rows ti*4..+3
    const int tj = t & 15;         // 0..15: cols tj*4..+3

    const float* __restrict__ A = m ? g_xs : x;
    const float* __restrict__ B = m ? g_lhT : g_hcT;
    float* __restrict__ outp = g_pd + (size_t)z * (NROWS * MCL);
    const int kbase = kh * KHALF;

    const int arow = t >> 2;        // 0..31
    const int acol = (t & 3) * 4;   // 0,4,8,12 (+16 second half)

    unsigned long long acc[4][2];
    #pragma unroll
    for (int r = 0; r < 4; r++) { acc[r][0] = 0ull; acc[r][1] = 0ull; }

    float4 a0, a1, bst[4];
    {
        const size_t ga = (size_t)(bi * 32 + arow) * CDIM + kbase + acol;
        a0 = *reinterpret_cast<const float4*>(A + ga);
        a1 = *reinterpret_cast<const float4*>(A + ga + 16);
        #pragma unroll
        for (int sbk = 0; sbk < 4; sbk++) {
            const int idx = t + 128 * sbk;
            const int kk = idx >> 4, jf = (idx & 15) * 4;
            bst[sbk] = *reinterpret_cast<const float4*>(
                B + (size_t)(kbase + kk) * MCL + bj * 64 + jf);
        }
    }

    for (int ch = 0; ch < KHALF / 32; ch++) {
        // store A duplicated: value v at (row, kk) -> sad[kk][2*row],[2*row+1]
        {
            const float av[8] = { a0.x, a0.y, a0.z, a0.w, a1.x, a1.y, a1.z, a1.w };
            #pragma unroll
            for (int q = 0; q < 4; q++) {
                *reinterpret_cast<float2*>(&sad[acol + q][2 * arow]) =
                    make_float2(av[q], av[q]);
                *reinterpret_cast<float2*>(&sad[acol + 16 + q][2 * arow]) =
                    make_float2(av[4 + q], av[4 + q]);
            }
        }
        #pragma unroll
        for (int sbk = 0; sbk < 4; sbk++) {
            const int idx = t + 128 * sbk;
            const int kk = idx >> 4, jf = (idx & 15) * 4;
            *reinterpret_cast<float4*>(&sb[kk][jf]) = bst[sbk];
        }
        __syncthreads();

        if (ch < KHALF / 32 - 1) {
            const int k0 = kbase + (ch + 1) * 32;
            const size_t ga = (size_t)(bi * 32 + arow) * CDIM + k0 + acol;
            a0 = *reinterpret_cast<const float4*>(A + ga);
            a1 = *reinterpret_cast<const float4*>(A + ga + 16);
            #pragma unroll
            for (int sbk = 0; sbk < 4; sbk++) {
                const int idx = t + 128 * sbk;
                const int kk = idx >> 4, jf = (idx & 15) * 4;
                bst[sbk] = *reinterpret_cast<const float4*>(
                    B + (size_t)(k0 + kk) * MCL + bj * 64 + jf);
            }
        }

        // zero-MOV inner loop: 3 LDS.128 + 8 FFMA2 per kk
        #pragma unroll
        for (int kk = 0; kk < 32; kk++) {
            const ulonglong2 aa = *reinterpret_cast<const ulonglong2*>(&sad[kk][ti * 8]);
            const ulonglong2 ab = *reinterpret_cast<const ulonglong2*>(&sad[kk][ti * 8 + 4]);
            const ulonglong2 bb = *reinterpret_cast<const ulonglong2*>(&sb[kk][tj * 4]);
            fma2(acc[0][0], aa.x, bb.x); fma2(acc[0][1], aa.x, bb.y);
            fma2(acc[1][0], aa.y, bb.x); fma2(acc[1][1], aa.y, bb.y);
            fma2(acc[2][0], ab.x, bb.x); fma2(acc[2][1], ab.x, bb.y);
            fma2(acc[3][0], ab.y, bb.x); fma2(acc[3][1], ab.y, bb.y);
        }
        __syncthreads();
    }

    // write 4x4 partial tile to plane z
    {
        const int ibase = bi * 32 + ti * 4;
        const int jbase = bj * 64 + tj * 4;
        #pragma unroll
        for (int r = 0; r < 4; r++) {
            float4 rv;
            upk2(acc[r][0], rv.x, rv.y);
            upk2(acc[r][1], rv.z, rv.w);
            *reinterpret_cast<float4*>(outp + (size_t)(ibase + r) * MCL + jbase) = rv;
        }
    }

    // ---- all 576 blocks rendezvous; then share the epilogue ----
    grid_sync_all();

    float* senth = (float*)&sad[0][0];                // [192]
    long long* sph = (long long*)&sb[0][0];           // [192]
    for (int c = t; c < MCL; c += 128) {
        senth[c] = g_enth[c];
        sph[c] = pids[(size_t)c * GK];
    }
    __syncthreads();

    const int blk = (bi * GBJ + bj) * NZ + z;         // 0..575
    // exactly one float4-group per thread: 576*128 = 73728 groups
    const int g = blk * 128 + t;
    const int i = g / 48;
    const int jf = (g % 48) * 4;

    float psum = 0.f, nsum = 0.f;
    int pcnt = 0, ncnt = 0;
    {
        const size_t base = (size_t)i * MCL + jf;
        const float4 p0 = *reinterpret_cast<const float4*>(g_pd + base);
        const float4 p1 = *reinterpret_cast<const float4*>(g_pd + (size_t)(NROWS * MCL) + base);
        const float4 p2 = *reinterpret_cast<const float4*>(g_pd + (size_t)(2 * NROWS * MCL) + base);
        const float4 p3 = *reinterpret_cast<const float4*>(g_pd + (size_t)(3 * NROWS * MCL) + base);
        const float rc = g_rowc[i];
        const long long pi = pids[i];
        const bool itop = i < MID_N;
        const float dv[4] = {
            rc + senth[jf + 0] - ((p0.x + p2.x) + (p1.x + p3.x)),
            rc + senth[jf + 1] - ((p0.y + p2.y) + (p1.y + p3.y)),
            rc + senth[jf + 2] - ((p0.z + p2.z) + (p1.z + p3.z)),
            rc + senth[jf + 3] - ((p0.w + p2.w) + (p1.w + p3.w)) };
        #pragma unroll
        for (int c = 0; c < 4; c++) {
            const bool mask = (pi == sph[jf + c]);
            const bool region = itop != ((jf + c) < MID_M);
            if (mask) {
                if (region) { psum += dv[c]; pcnt++; }
            } else {
                nsum += fmaxf(MARGIN_KL - dv[c], 0.f);
                ncnt++;
            }
        }
    }

    #pragma unroll
    for (int o = 16; o; o >>= 1) {
        psum += __shfl_xor_sync(0xffffffffu, psum, o);
        nsum += __shfl_xor_sync(0xffffffffu, nsum, o);
        pcnt += __shfl_xor_sync(0xffffffffu, pcnt, o);
        ncnt += __shfl_xor_sync(0xffffffffu, ncnt, o);
    }
    const int w = t >> 5;
    if ((t & 31) == 0) { rp[w] = psum; rn[w] = nsum; cp[w] = pcnt; cn[w] = ncnt; }
    __syncthreads();
    if (t == 0) {
        g_part[blk * 4 + 0] = (rp[0] + rp[1]) + (rp[2] + rp[3]);
        g_part[blk * 4 + 1] = (rn[0] + rn[1]) + (rn[2] + rn[3]);
        g_part[blk * 4 + 2] = (float)((cp[0] + cp[1]) + (cp[2] + cp[3]));
        g_part[blk * 4 + 3] = (float)((cn[0] + cn[1]) + (cn[2] + cn[3]));
        __threadfence();
        slast = (atomicAdd(&g_ctr, 1u) == NBLK - 1);
    }
    __syncthreads();

    if (slast) {
        __threadfence();
        float ps = 0.f, ns = 0.f, pc = 0.f, nc = 0.f;
        for (int b2 = t; b2 < NBLK; b2 += 128) {
            ps += g_part[b2 * 4 + 0];
            ns += g_part[b2 * 4 + 1];
            pc += g_part[b2 * 4 + 2];
            nc += g_part[b2 * 4 + 3];
        }
        #pragma unroll
        for (int o = 16; o; o >>= 1) {
            ps += __shfl_xor_sync(0xffffffffu, ps, o);
            ns += __shfl_xor_sync(0xffffffffu, ns, o);
            pc += __shfl_xor_sync(0xffffffffu, pc, o);
            nc += __shfl_xor_sync(0xffffffffu, nc, o);
        }
        if ((t & 31) == 0) { rp[w] = ps; rn[w] = ns; cp[w] = (int)pc; cn[w] = (int)nc; }
        __syncthreads();
        if (t == 0) {
            const float fps = (rp[0] + rp[1]) + (rp[2] + rp[3]);
            const float fns = (rn[0] + rn[1]) + (rn[2] + rn[3]);
            const float fpc = (float)((cp[0] + cp[1]) + (cp[2] + cp[3]));
            const float fnc = (float)((cn[0] + cn[1]) + (cn[2] + cn[3]));
            out[0] = fps / fmaxf(fpc, 1.0f) + fns / fmaxf(fnc, 1.0f);
            g_ctr = 0;   // reset for next graph replay
        }
    }
}

// ---------------------------------------------------------------------------
extern "C" void kernel_launch(void* const* d_in, const int* in_sizes, int n_in,
                              void* d_out, int out_size) {
    const float* x = (const float*)d_in[0];
    const long long* pids = (const long long*)d_in[1];
    (void)in_sizes; (void)n_in; (void)out_size;

    k_stats<<<MCL, 256>>>(x);
    dim3 gg(GBI, GBJ, NZ);
    k_gemm_epi<<<gg, 128>>>(x, pids, (float*)d_out);
}

// round 8
// speedup vs baseline: 1.5627x; 1.5627x over previous
#include <cuda_runtime.h>
#include <cuda_bf16.h>

// Problem constants (fixed: P=64, K=8, C=512, N=3*P*K=1536)
#define NROWS 1536
#define CDIM  512
#define MCL   192
#define GK    8
#define MARGIN_KL 6.0f
#define MID_N 1024
#define MID_M 128
#define GBI   48
#define GBJ   3
#define NBLK  (GBI * GBJ)     // 144 mma blocks

// bf16 split planes: A-side [i][k] = {x_hi, x_lo, xs_hi, xs_lo}
__device__ __nv_bfloat16 g_A[4][NROWS * CDIM];
// B-side [j][k] = {hcen_hi, hcen_lo, logh_hi, logh_lo}
__device__ __nv_bfloat16 g_B[4][MCL * CDIM];
__device__ float g_rowc[NROWS];     // ent_x + lse
__device__ float g_enth[MCL];
__device__ float g_part[NBLK * 4];
__device__ unsigned int g_ctr = 0;

// ---------------- bf16 split helpers ----------------
__device__ __forceinline__ unsigned int pkbf(float a, float b) {
    __nv_bfloat162 h = __floats2bfloat162_rn(a, b);   // low half = a
    return *reinterpret_cast<unsigned int*>(&h);
}
__device__ __forceinline__ float bfres(float v) {
    return v - __bfloat162float(__float2bfloat16_rn(v));
}

// ---------------- bf16 mma m16n8k16 (fp32 accum) ----------------
__device__ __forceinline__ void mma16816(float* d, const unsigned int* a,
                                         const unsigned int* b) {
    asm volatile(
        "mma.sync.aligned.m16n8k16.row.col.f32.bf16.bf16.f32 "
        "{%0,%1,%2,%3}, {%4,%5,%6,%7}, {%8,%9}, {%0,%1,%2,%3};"
        : "+f"(d[0]), "+f"(d[1]), "+f"(d[2]), "+f"(d[3])
        : "r"(a[0]), "r"(a[1]), "r"(a[2]), "r"(a[3]), "r"(b[0]), "r"(b[1]));
}

// ---------------------------------------------------------------------------
// Kernel 1: softmax stats + centers; emits bf16 hi/lo planes.
// 192 blocks x 256 threads; warp w handles row 8*j + w.
// ---------------------------------------------------------------------------
__global__ void __launch_bounds__(256) k_stats(const float* __restrict__ x) {
    __shared__ float sxs[8][516];
    __shared__ float shc[512], slh[512];
    __shared__ float sred[8];
    const int j = blockIdx.x;
    const int t = threadIdx.x;
    const int w = t >> 5, lane = t & 31;
    const int row = j * GK + w;

    const float4* xr = reinterpret_cast<const float4*>(x + (size_t)row * CDIM);
    float4 v[4];
    #pragma unroll
    for (int q = 0; q < 4; q++) v[q] = xr[lane + 32 * q];

    float mx = -1e30f;
    #pragma unroll
    for (int q = 0; q < 4; q++)
        mx = fmaxf(mx, fmaxf(fmaxf(v[q].x, v[q].y), fmaxf(v[q].z, v[q].w)));
    #pragma unroll
    for (int o = 16; o; o >>= 1) mx = fmaxf(mx, __shfl_xor_sync(0xffffffffu, mx, o));

    float4 e[4];
    float s = 0.f;
    #pragma unroll
    for (int q = 0; q < 4; q++) {
        e[q].x = __expf(v[q].x - mx); e[q].y = __expf(v[q].y - mx);
        e[q].z = __expf(v[q].z - mx); e[q].w = __expf(v[q].w - mx);
        s += (e[q].x + e[q].y) + (e[q].z + e[q].w);
    }
    #pragma unroll
    for (int o = 16; o; o >>= 1) s += __shfl_xor_sync(0xffffffffu, s, o);

    const float lse = mx + __logf(s);
    const float inv = 1.0f / s;

    float* sx = &sxs[w][0];
    float ent = 0.f;
    #pragma unroll
    for (int q = 0; q < 4; q++) {
        float4 p = make_float4(e[q].x * inv, e[q].y * inv, e[q].z * inv, e[q].w * inv);
        reinterpret_cast<float4*>(sx)[lane + 32 * q] = p;
        const int kb = 4 * (lane + 32 * q);
        const size_t off = (size_t)row * CDIM + kb;
        // x hi/lo
        *reinterpret_cast<uint2*>(&g_A[0][off]) =
            make_uint2(pkbf(v[q].x, v[q].y), pkbf(v[q].z, v[q].w));
        *reinterpret_cast<uint2*>(&g_A[1][off]) =
            make_uint2(pkbf(bfres(v[q].x), bfres(v[q].y)),
                       pkbf(bfres(v[q].z), bfres(v[q].w)));
        // xs hi/lo
        *reinterpret_cast<uint2*>(&g_A[2][off]) =
            make_uint2(pkbf(p.x, p.y), pkbf(p.z, p.w));
        *reinterpret_cast<uint2*>(&g_A[3][off]) =
            make_uint2(pkbf(bfres(p.x), bfres(p.y)),
                       pkbf(bfres(p.z), bfres(p.w)));
        ent += p.x * (v[q].x - lse) + p.y * (v[q].y - lse)
             + p.z * (v[q].z - lse) + p.w * (v[q].w - lse);
    }
    #pragma unroll
    for (int o = 16; o; o >>= 1) ent += __shfl_xor_sync(0xffffffffu, ent, o);
    if (lane == 0) g_rowc[row] = ent + lse;

    __syncthreads();

    // centers into smem
    float entp = 0.f;
    #pragma unroll
    for (int h = 0; h < 2; h++) {
        const int c = t + 256 * h;
        float hc = 0.f;
        #pragma unroll
        for (int r = 0; r < GK; r++) hc += sxs[r][c];
        hc *= (1.0f / (float)GK);
        const float l = __logf(fmaxf(hc, 1e-9f));
        shc[c] = hc;
        slh[c] = l;
        entp += hc * l;
    }
    #pragma unroll
    for (int o = 16; o; o >>= 1) entp += __shfl_xor_sync(0xffffffffu, entp, o);
    if (lane == 0) sred[w] = entp;
    __syncthreads();
    if (t == 0) {
        float eh = 0.f;
        #pragma unroll
        for (int r = 0; r < 8; r++) eh += sred[r];
        g_enth[j] = eh;
    }

    // coalesced bf16 hi/lo row writes: thread t handles cols {2t, 2t+1}
    {
        const float h0 = shc[2 * t],  h1 = shc[2 * t + 1];
        const float l0 = slh[2 * t],  l1 = slh[2 * t + 1];
        const size_t off = (size_t)j * CDIM + 2 * t;
        *reinterpret_cast<unsigned int*>(&g_B[0][off]) = pkbf(h0, h1);
        *reinterpret_cast<unsigned int*>(&g_B[1][off]) = pkbf(bfres(h0), bfres(h1));
        *reinterpret_cast<unsigned int*>(&g_B[2][off]) = pkbf(l0, l1);
        *reinterpret_cast<unsigned int*>(&g_B[3][off]) = pkbf(bfres(l0), bfres(l1));
    }
}

// ---------------------------------------------------------------------------
// Kernel 2: bf16-split tensor GEMM + fused loss epilogue.
// Grid (48,3) = 144 CTAs x 128 threads. CTA tile 32x64; warp tile 16x32.
// dist = rowc[i] + enth[j] - (x.hcen + xs.logh), 3-term bf16 split per product.
// ---------------------------------------------------------------------------
__global__ void __launch_bounds__(128) k_mma(const long long* __restrict__ pids,
                                             float* __restrict__ out) {
    __shared__ __align__(16) __nv_bfloat16 sA[4][32][40];
    __shared__ __align__(16) __nv_bfloat16 sB[4][64][40];
    __shared__ float rp[4], rn[4];
    __shared__ int cp[4], cn[4];
    __shared__ bool slast;

    const int bi = blockIdx.x;     // 0..47
    const int bj = blockIdx.y;     // 0..2
    const int t  = threadIdx.x;
    const int w  = t >> 5, lane = t & 31;
    const int g  = lane >> 2, t4 = lane & 3;
    const int wm = w >> 1;         // warp m-half (0/1)
    const int wn = w & 1;          // warp n-half (0/1)

    float acc0[4][4], acc1[4][4];
    #pragma unroll
    for (int nt = 0; nt < 4; nt++)
        #pragma unroll
        for (int c = 0; c < 4; c++) { acc0[nt][c] = 0.f; acc1[nt][c] = 0.f; }

    // staging mappings (uint4 = 8 bf16)
    const int arow = t >> 2, aseg = t & 3;   // A: 1 uint4 per array per thread
    uint4 pa[4], pb[4][2];

    // prefetch chunk 0
    #pragma unroll
    for (int arr = 0; arr < 4; arr++) {
        pa[arr] = reinterpret_cast<const uint4*>(g_A[arr])
                      [(size_t)(bi * 32 + arow) * 64 + aseg];
        #pragma unroll
        for (int q = 0; q < 2; q++) {
            const int idx = t + 128 * q;
            pb[arr][q] = reinterpret_cast<const uint4*>(g_B[arr])
                             [(size_t)(bj * 64 + (idx >> 2)) * 64 + (idx & 3)];
        }
    }

    for (int ch = 0; ch < 16; ch++) {
        #pragma unroll
        for (int arr = 0; arr < 4; arr++) {
            *reinterpret_cast<uint4*>(&sA[arr][arow][aseg * 8]) = pa[arr];
            #pragma unroll
            for (int q = 0; q < 2; q++) {
                const int idx = t + 128 * q;
                *reinterpret_cast<uint4*>(&sB[arr][idx >> 2][(idx & 3) * 8]) = pb[arr][q];
            }
        }
        __syncthreads();

        if (ch < 15) {
            const int ko = (ch + 1) * 4;   // uint4 offset for next chunk
            #pragma unroll
            for (int arr = 0; arr < 4; arr++) {
                pa[arr] = reinterpret_cast<const uint4*>(g_A[arr])
                              [(size_t)(bi * 32 + arow) * 64 + ko + aseg];
                #pragma unroll
                for (int q = 0; q < 2; q++) {
                    const int idx = t + 128 * q;
                    pb[arr][q] = reinterpret_cast<const uint4*>(g_B[arr])
                                     [(size_t)(bj * 64 + (idx >> 2)) * 64 + ko + (idx & 3)];
                }
            }
        }

        #pragma unroll
        for (int kk2 = 0; kk2 < 2; kk2++) {
            const int c0 = kk2 * 16 + 2 * t4;
            const int c1 = c0 + 8;
            const int r0 = wm * 16 + g, r1 = r0 + 8;

            unsigned int axh[4], axl[4], ash[4], asl[4];
            axh[0] = *reinterpret_cast<unsigned int*>(&sA[0][r0][c0]);
            axh[1] = *reinterpret_cast<unsigned int*>(&sA[0][r1][c0]);
            axh[2] = *reinterpret_cast<unsigned int*>(&sA[0][r0][c1]);
            axh[3] = *reinterpret_cast<unsigned int*>(&sA[0][r1][c1]);
            axl[0] = *reinterpret_cast<unsigned int*>(&sA[1][r0][c0]);
            axl[1] = *reinterpret_cast<unsigned int*>(&sA[1][r1][c0]);
            axl[2] = *reinterpret_cast<unsigned int*>(&sA[1][r0][c1]);
            axl[3] = *reinterpret_cast<unsigned int*>(&sA[1][r1][c1]);
            ash[0] = *reinterpret_cast<unsigned int*>(&sA[2][r0][c0]);
            ash[1] = *reinterpret_cast<unsigned int*>(&sA[2][r1][c0]);
            ash[2] = *reinterpret_cast<unsigned int*>(&sA[2][r0][c1]);
            ash[3] = *reinterpret_cast<unsigned int*>(&sA[2][r1][c1]);
            asl[0] = *reinterpret_cast<unsigned int*>(&sA[3][r0][c0]);
            asl[1] = *reinterpret_cast<unsigned int*>(&sA[3][r1][c0]);
            asl[2] = *reinterpret_cast<unsigned int*>(&sA[3][r0][c1]);
            asl[3] = *reinterpret_cast<unsigned int*>(&sA[3][r1][c1]);

            unsigned int bhh[4][2], bhl[4][2], blh[4][2], bll[4][2];
            #pragma unroll
            for (int nt = 0; nt < 4; nt++) {
                const int nn = wn * 32 + nt * 8 + g;
                bhh[nt][0] = *reinterpret_cast<unsigned int*>(&sB[0][nn][c0]);
                bhh[nt][1] = *reinterpret_cast<unsigned int*>(&sB[0][nn][c1]);
                bhl[nt][0] = *reinterpret_cast<unsigned int*>(&sB[1][nn][c0]);
                bhl[nt][1] = *reinterpret_cast<unsigned int*>(&sB[1][nn][c1]);
                blh[nt][0] = *reinterpret_cast<unsigned int*>(&sB[2][nn][c0]);
                blh[nt][1] = *reinterpret_cast<unsigned int*>(&sB[2][nn][c1]);
                bll[nt][0] = *reinterpret_cast<unsigned int*>(&sB[3][nn][c0]);
                bll[nt][1] = *reinterpret_cast<unsigned int*>(&sB[3][nn][c1]);
            }

            // 24 mmas, 8 independent accumulator streams round-robin
            #pragma unroll
            for (int nt = 0; nt < 4; nt++) mma16816(acc0[nt], axh, bhh[nt]);
            #pragma unroll
            for (int nt = 0; nt < 4; nt++) mma16816(acc1[nt], ash, blh[nt]);
            #pragma unroll
            for (int nt = 0; nt < 4; nt++) mma16816(acc0[nt], axh, bhl[nt]);
            #pragma unroll
            for (int nt = 0; nt < 4; nt++) mma16816(acc1[nt], ash, bll[nt]);
            #pragma unroll
            for (int nt = 0; nt < 4; nt++) mma16816(acc0[nt], axl, bhh[nt]);
            #pragma unroll
            for (int nt = 0; nt < 4; nt++) mma16816(acc1[nt], asl, blh[nt]);
        }
        __syncthreads();
    }

    // ---- fused epilogue: tables into reused smem ----
    float* senth = reinterpret_cast<float*>(&sA[0][0][0]);   // [192]
    float* srowc = senth + 192;                              // [32]
    int* sphc = reinterpret_cast<int*>(srowc + 32);          // [192]
    int* spid = sphc + 192;                                  // [32]
    for (int c = t; c < MCL; c += 128) {
        senth[c] = g_enth[c];
        sphc[c] = (int)pids[(size_t)c * GK];
    }
    if (t < 32) {
        srowc[t] = g_rowc[bi * 32 + t];
        spid[t] = (int)pids[bi * 32 + t];
    }
    __syncthreads();

    float psum = 0.f, nsum = 0.f;
    int pcnt = 0, ncnt = 0;
    #pragma unroll
    for (int nt = 0; nt < 4; nt++) {
        const int jl = wn * 32 + nt * 8 + 2 * t4;
        const int jg = bj * 64 + jl;
        #pragma unroll
        for (int c = 0; c < 4; c++) {
            const int il = wm * 16 + g + (c >> 1) * 8;   // c2,c3 are +8 rows
            const int jj = jg + (c & 1);
            const int i = bi * 32 + il;
            const float dist = srowc[il] + senth[jj] - (acc0[nt][c] + acc1[nt][c]);
            const bool mask = (spid[il] == sphc[jj]);
            const bool region = (i < MID_N) != (jj < MID_M);
            if (mask) {
                if (region) { psum += dist; pcnt++; }
            } else {
                nsum += fmaxf(MARGIN_KL - dist, 0.f);
                ncnt++;
            }
        }
    }

    #pragma unroll
    for (int o = 16; o; o >>= 1) {
        psum += __shfl_xor_sync(0xffffffffu, psum, o);
        nsum += __shfl_xor_sync(0xffffffffu, nsum, o);
        pcnt += __shfl_xor_sync(0xffffffffu, pcnt, o);
        ncnt += __shfl_xor_sync(0xffffffffu, ncnt, o);
    }
    if (lane == 0) { rp[w] = psum; rn[w] = nsum; cp[w] = pcnt; cn[w] = ncnt; }
    __syncthreads();
    const int blk = bi * GBJ + bj;
    if (t == 0) {
        g_part[blk * 4 + 0] = (rp[0] + rp[1]) + (rp[2] + rp[3]);
        g_part[blk * 4 + 1] = (rn[0] + rn[1]) + (rn[2] + rn[3]);
        g_part[blk * 4 + 2] = (float)((cp[0] + cp[1]) + (cp[2] + cp[3]));
        g_part[blk * 4 + 3] = (float)((cn[0] + cn[1]) + (cn[2] + cn[3]));
        __threadfence();
        slast = (atomicAdd(&g_ctr, 1u) == NBLK - 1);
    }
    __syncthreads();

    if (slast) {
        __threadfence();
        float ps = 0.f, ns = 0.f, pc = 0.f, nc = 0.f;
        for (int b2 = t; b2 < NBLK; b2 += 128) {
            ps += g_part[b2 * 4 + 0];
            ns += g_part[b2 * 4 + 1];
            pc += g_part[b2 * 4 + 2];
            nc += g_part[b2 * 4 + 3];
        }
        #pragma unroll
        for (int o = 16; o; o >>= 1) {
            ps += __shfl_xor_sync(0xffffffffu, ps, o);
            ns += __shfl_xor_sync(0xffffffffu, ns, o);
            pc += __shfl_xor_sync(0xffffffffu, pc, o);
            nc += __shfl_xor_sync(0xffffffffu, nc, o);
        }
        if (lane == 0) { rp[w] = ps; rn[w] = ns; cp[w] = (int)pc; cn[w] = (int)nc; }
        __syncthreads();
        if (t == 0) {
            const float fps = (rp[0] + rp[1]) + (rp[2] + rp[3]);
            const float fns = (rn[0] + rn[1]) + (rn[2] + rn[3]);
            const float fpc = (float)((cp[0] + cp[1]) + (cp[2] + cp[3]));
            const float fnc = (float)((cn[0] + cn[1]) + (cn[2] + cn[3]));
            out[0] = fps / fmaxf(fpc, 1.0f) + fns / fmaxf(fnc, 1.0f);
            g_ctr = 0;   // reset for next graph replay
        }
    }
}

// ---------------------------------------------------------------------------
extern "C" void kernel_launch(void* const* d_in, const int* in_sizes, int n_in,
                              void* d_out, int out_size) {
    const float* x = (const float*)d_in[0];
    const long long* pids = (const long long*)d_in[1];
    (void)in_sizes; (void)n_in; (void)out_size;

    k_stats<<<MCL, 256>>>(x);
    dim3 gg(GBI, GBJ);
    k_mma<<<gg, 128>>>(pids, (float*)d_out);
}